// round 11
// baseline (speedup 1.0000x reference)
#include <cuda_runtime.h>
#include <cuda_bf16.h>
#include <cstdint>
#include <cstdio>

// ---------------- problem constants ----------------
#define BIMG   16
#define HH     128
#define WW_    128
#define CC     192
#define HEADS  6
#define HD     32
#define WIN    8
#define SHIFT  4
#define NTOK   (BIMG * HH * WW_)              // 262144 tokens
#define NWIN   (BIMG * (HH/WIN) * (WW_/WIN))  // 4096 windows
#define NN     (WIN * WIN)                    // 64 tokens per window

// ---------------- scratch ----------------
__device__ float g_x1 [ (size_t)NTOK * CC ];        // residual-1 (token order)

// ---------------- helpers ----------------
__device__ __forceinline__ float tf32f(float x) {
    uint32_t u;
    asm("cvt.rna.tf32.f32 %0, %1;" : "=r"(u) : "f"(x));
    return __uint_as_float(u);
}

__device__ __forceinline__ void mma_tf32(float c[4], const uint32_t a[4], const uint32_t b[2]) {
    asm volatile(
        "mma.sync.aligned.m16n8k8.row.col.f32.tf32.tf32.f32 "
        "{%0,%1,%2,%3}, {%4,%5,%6,%7}, {%8,%9}, {%0,%1,%2,%3};"
        : "+f"(c[0]), "+f"(c[1]), "+f"(c[2]), "+f"(c[3])
        : "r"(a[0]), "r"(a[1]), "r"(a[2]), "r"(a[3]), "r"(b[0]), "r"(b[1]));
}

// exp(x) for |x| <= 0.1768: degree-5 Taylor, rel err < 5e-9
__device__ __forceinline__ float exp_small(float x) {
    float e = 8.3333333e-3f;
    e = e * x + 4.1666667e-2f;
    e = e * x + 1.6666667e-1f;
    e = e * x + 0.5f;
    e = e * x + 1.0f;
    e = e * x + 1.0f;
    return e;
}

// window-order token -> original token row (shift + window reverse)
__device__ __forceinline__ size_t win_to_tok(int tok) {
    int win = tok >> 6, n = tok & 63;
    int b   = win >> 8;
    int wh  = (win >> 4) & 15;
    int ww  = win & 15;
    int r   = n >> 3, c = n & 7;
    int i = (wh*WIN + r + SHIFT) & 127;
    int j = (ww*WIN + c + SHIFT) & 127;
    return (size_t)b * (HH*WW_) + (size_t)i * WW_ + j;
}

// ================= MEGAKERNEL: LN1 + QKV + attention + proj + residual =================
// One block per window (64 tokens), 256 threads, qkv never leaves smem.
// smem (floats): As/Os [64*196] | Qn [64*196] | Kn [64*196] | Vall [64*196]
//                Bs [2*192*20]  (overlaid by Ps[64*68]+Ssum[128] during attention)
#define R196 (64*196)
__global__ __launch_bounds__(256) void swin_part1_k(
    const float* __restrict__ x, const float* __restrict__ n1g,
    const float* __restrict__ n1b, const float* __restrict__ qkv_w,
    const float* __restrict__ qkv_b, const float* __restrict__ proj_w,
    const float* __restrict__ proj_b, float* __restrict__ x1)
{
    extern __shared__ float sm[];
    float* As   = sm;                 // later Os
    float* Qn   = sm + R196;
    float* Kn   = sm + 2*R196;
    float* Vall = sm + 3*R196;
    float* Bs   = sm + 4*R196;        // 7680 floats
    float* Ps   = Bs;                 // overlay (attention phase)
    float* Ssum = Bs + 64*68;

    const int win  = blockIdx.x;
    const int tok0 = win * 64;
    const int tid  = threadIdx.x;
    const int lane = tid & 31;
    const int warp = tid >> 5;
    const int qrow = lane >> 2;
    const int qcol = lane & 3;

    // ---------- LN1 staging with shift-gather (each warp 8 rows) ----------
    #pragma unroll
    for (int rr = 0; rr < 8; ++rr) {
        int row = warp*8 + rr;
        const float* src = x + win_to_tok(tok0 + row) * CC;
        float v[6];
        float s = 0.f;
        #pragma unroll
        for (int u = 0; u < 6; ++u) { v[u] = src[lane + u*32]; s += v[u]; }
        #pragma unroll
        for (int o = 16; o; o >>= 1) s += __shfl_xor_sync(0xffffffffu, s, o);
        float mean = s * (1.f/192.f);
        float var = 0.f;
        #pragma unroll
        for (int u = 0; u < 6; ++u) { float d = v[u]-mean; var += d*d; }
        #pragma unroll
        for (int o = 16; o; o >>= 1) var += __shfl_xor_sync(0xffffffffu, var, o);
        var *= (1.f/192.f);
        float rstd = rsqrtf(var + 1e-5f);
        #pragma unroll
        for (int u = 0; u < 6; ++u) {
            int ch = lane + u*32;
            As[row*196 + ch] = tf32f((v[u]-mean)*rstd*n1g[ch] + n1b[ch]);
        }
    }
    __syncthreads();

    // ---------- QKV GEMM: 3 chunks of 192 (Q, K, V) ----------
    {
        const int wm = warp & 1;          // 2 m-tiles of 32
        const int wn = warp >> 1;         // 4 n-groups of 48
        for (int nc = 0; nc < 3; ++nc) {
            float acc[2][6][4];
            #pragma unroll
            for (int i = 0; i < 2; ++i)
                #pragma unroll
                for (int j = 0; j < 6; ++j)
                    #pragma unroll
                    for (int r = 0; r < 4; ++r) acc[i][j][r] = 0.f;

            float4 wreg[3];
            #pragma unroll
            for (int i = 0; i < 3; ++i) {
                int idx = i*256 + tid;
                int r2 = idx >> 2, q2 = (idx & 3) << 2;
                wreg[i] = *(const float4*)(qkv_w + (size_t)(nc*192 + r2) * CC + q2);
            }
            #pragma unroll
            for (int i = 0; i < 3; ++i) {
                int idx = i*256 + tid;
                int r2 = idx >> 2, q2 = (idx & 3) << 2;
                float* d = Bs + 0*192*20 + r2*20 + q2;
                d[0] = tf32f(wreg[i].x); d[1] = tf32f(wreg[i].y);
                d[2] = tf32f(wreg[i].z); d[3] = tf32f(wreg[i].w);
            }
            __syncthreads();

            int buf = 0;
            for (int k0 = 0; ; k0 += 16) {
                const bool more = (k0 + 16) < CC;
                if (more) {
                    #pragma unroll
                    for (int i = 0; i < 3; ++i) {
                        int idx = i*256 + tid;
                        int r2 = idx >> 2, q2 = (idx & 3) << 2;
                        wreg[i] = *(const float4*)(qkv_w + (size_t)(nc*192 + r2) * CC + k0 + 16 + q2);
                    }
                }
                #pragma unroll
                for (int ks = 0; ks < 16; ks += 8) {
                    uint32_t afr[2][4];
                    #pragma unroll
                    for (int mt = 0; mt < 2; ++mt) {
                        int r = wm*32 + mt*16 + qrow;
                        int k = k0 + ks + qcol;
                        afr[mt][0] = __float_as_uint(As[r*196     + k]);
                        afr[mt][1] = __float_as_uint(As[(r+8)*196 + k]);
                        afr[mt][2] = __float_as_uint(As[r*196     + k + 4]);
                        afr[mt][3] = __float_as_uint(As[(r+8)*196 + k + 4]);
                    }
                    uint32_t bfr[6][2];
                    #pragma unroll
                    for (int nt = 0; nt < 6; ++nt) {
                        int n = wn*48 + nt*8 + qrow;
                        bfr[nt][0] = __float_as_uint(Bs[buf*192*20 + n*20 + ks + qcol]);
                        bfr[nt][1] = __float_as_uint(Bs[buf*192*20 + n*20 + ks + qcol + 4]);
                    }
                    #pragma unroll
                    for (int mt = 0; mt < 2; ++mt)
                        #pragma unroll
                        for (int nt = 0; nt < 6; ++nt)
                            mma_tf32(acc[mt][nt], afr[mt], bfr[nt]);
                }
                if (!more) break;
                const int ob = buf ^ 1;
                #pragma unroll
                for (int i = 0; i < 3; ++i) {
                    int idx = i*256 + tid;
                    int r2 = idx >> 2, q2 = (idx & 3) << 2;
                    float* d = Bs + ob*192*20 + r2*20 + q2;
                    d[0] = tf32f(wreg[i].x); d[1] = tf32f(wreg[i].y);
                    d[2] = tf32f(wreg[i].z); d[3] = tf32f(wreg[i].w);
                }
                __syncthreads();
                buf = ob;
            }
            __syncthreads();   // all Bs reads done before next chunk restages

            // epilogue: +bias -> smem (Q,K raw fp32; V tf32)
            float* dst = (nc == 0) ? Qn : (nc == 1) ? Kn : Vall;
            #pragma unroll
            for (int mt = 0; mt < 2; ++mt) {
                #pragma unroll
                for (int half = 0; half < 2; ++half) {
                    int row = wm*32 + mt*16 + qrow + half*8;
                    #pragma unroll
                    for (int nt = 0; nt < 6; ++nt) {
                        int col = wn*48 + nt*8 + qcol*2;
                        float v0 = acc[mt][nt][half*2+0] + qkv_b[nc*192 + col];
                        float v1 = acc[mt][nt][half*2+1] + qkv_b[nc*192 + col + 1];
                        if (nc == 2) { v0 = tf32f(v0); v1 = tf32f(v1); }
                        *(float2*)&dst[row*196 + col] = make_float2(v0, v1);
                    }
                }
            }
        }
    }
    __syncthreads();   // Q/K/V fully written

    // ---------- l2-normalize Q (x scale) and K in-place (tf32) ----------
    {
        const int sr = tid >> 2;
        const int sq = tid & 3;
        const float scale = 0.17677669529663687f;   // 1/sqrt(32)
        #pragma unroll
        for (int h = 0; h < HEADS; ++h) {
            int base = sr*196 + h*HD + sq*8;
            float4 qa = *(const float4*)&Qn[base];
            float4 qb = *(const float4*)&Qn[base + 4];
            float ss = qa.x*qa.x + qa.y*qa.y + qa.z*qa.z + qa.w*qa.w
                     + qb.x*qb.x + qb.y*qb.y + qb.z*qb.z + qb.w*qb.w;
            ss += __shfl_xor_sync(0xffffffffu, ss, 1);
            ss += __shfl_xor_sync(0xffffffffu, ss, 2);
            float invq = scale / fmaxf(sqrtf(ss), 1e-12f);
            *(float4*)&Qn[base] = make_float4(tf32f(qa.x*invq), tf32f(qa.y*invq),
                                              tf32f(qa.z*invq), tf32f(qa.w*invq));
            *(float4*)&Qn[base+4] = make_float4(tf32f(qb.x*invq), tf32f(qb.y*invq),
                                                tf32f(qb.z*invq), tf32f(qb.w*invq));

            float4 ka = *(const float4*)&Kn[base];
            float4 kb = *(const float4*)&Kn[base + 4];
            float sk = ka.x*ka.x + ka.y*ka.y + ka.z*ka.z + ka.w*ka.w
                     + kb.x*kb.x + kb.y*kb.y + kb.z*kb.z + kb.w*kb.w;
            sk += __shfl_xor_sync(0xffffffffu, sk, 1);
            sk += __shfl_xor_sync(0xffffffffu, sk, 2);
            float invk = 1.f / fmaxf(sqrtf(sk), 1e-12f);
            *(float4*)&Kn[base] = make_float4(tf32f(ka.x*invk), tf32f(ka.y*invk),
                                              tf32f(ka.z*invk), tf32f(ka.w*invk));
            *(float4*)&Kn[base+4] = make_float4(tf32f(kb.x*invk), tf32f(kb.y*invk),
                                                tf32f(kb.z*invk), tf32f(kb.w*invk));
        }
    }
    __syncthreads();

    // ---------- attention per head (8 warps: 4 m-tiles x 2 n-halves) ----------
    {
        const int wm = warp >> 1;
        const int wn = warp & 1;
        for (int h = 0; h < HEADS; ++h) {
            // S = Q_h @ K_h^T  (warp m16 x n32, K=32)
            float c[4][4];
            #pragma unroll
            for (int nt = 0; nt < 4; ++nt)
                #pragma unroll
                for (int i = 0; i < 4; ++i) c[nt][i] = 0.f;
            #pragma unroll
            for (int ks = 0; ks < 32; ks += 8) {
                uint32_t afr[4];
                int r = wm*16 + qrow;
                afr[0] = __float_as_uint(Qn[r*196     + h*HD + ks + qcol    ]);
                afr[1] = __float_as_uint(Qn[(r+8)*196 + h*HD + ks + qcol    ]);
                afr[2] = __float_as_uint(Qn[r*196     + h*HD + ks + qcol + 4]);
                afr[3] = __float_as_uint(Qn[(r+8)*196 + h*HD + ks + qcol + 4]);
                #pragma unroll
                for (int nt = 0; nt < 4; ++nt) {
                    uint32_t bfr[2];
                    int n = wn*32 + nt*8 + qrow;
                    bfr[0] = __float_as_uint(Kn[n*196 + h*HD + ks + qcol    ]);
                    bfr[1] = __float_as_uint(Kn[n*196 + h*HD + ks + qcol + 4]);
                    mma_tf32(c[nt], afr, bfr);
                }
            }

            float s0 = 0.f, s1 = 0.f;
            #pragma unroll
            for (int nt = 0; nt < 4; ++nt) {
                c[nt][0] = exp_small(c[nt][0]);
                c[nt][1] = exp_small(c[nt][1]);
                c[nt][2] = exp_small(c[nt][2]);
                c[nt][3] = exp_small(c[nt][3]);
                s0 += c[nt][0] + c[nt][1];
                s1 += c[nt][2] + c[nt][3];
            }
            s0 += __shfl_xor_sync(0xffffffffu, s0, 1);
            s0 += __shfl_xor_sync(0xffffffffu, s0, 2);
            s1 += __shfl_xor_sync(0xffffffffu, s1, 1);
            s1 += __shfl_xor_sync(0xffffffffu, s1, 2);
            if (qcol == 0) {
                Ssum[wn*64 + wm*16 + qrow    ] = s0;
                Ssum[wn*64 + wm*16 + qrow + 8] = s1;
            }
            #pragma unroll
            for (int nt = 0; nt < 4; ++nt) {
                int col = wn*32 + nt*8 + 2*qcol;
                *(float2*)&Ps[(wm*16 + qrow    )*68 + col] =
                    make_float2(tf32f(c[nt][0]), tf32f(c[nt][1]));
                *(float2*)&Ps[(wm*16 + qrow + 8)*68 + col] =
                    make_float2(tf32f(c[nt][2]), tf32f(c[nt][3]));
            }
            __syncthreads();

            // O = P @ V_h  (warp m16 x n16, K=64); V read token-major from Vall
            float o[2][4];
            #pragma unroll
            for (int nt = 0; nt < 2; ++nt)
                #pragma unroll
                for (int i = 0; i < 4; ++i) o[nt][i] = 0.f;
            #pragma unroll
            for (int ks = 0; ks < 64; ks += 8) {
                uint32_t afr[4];
                int r = wm*16 + qrow;
                afr[0] = __float_as_uint(Ps[r*68     + ks + qcol    ]);
                afr[1] = __float_as_uint(Ps[(r+8)*68 + ks + qcol    ]);
                afr[2] = __float_as_uint(Ps[r*68     + ks + qcol + 4]);
                afr[3] = __float_as_uint(Ps[(r+8)*68 + ks + qcol + 4]);
                #pragma unroll
                for (int nt = 0; nt < 2; ++nt) {
                    uint32_t bfr[2];
                    int n = wn*16 + nt*8 + qrow;     // dim within head
                    bfr[0] = __float_as_uint(Vall[(ks + qcol    )*196 + h*HD + n]);
                    bfr[1] = __float_as_uint(Vall[(ks + qcol + 4)*196 + h*HD + n]);
                    mma_tf32(o[nt], afr, bfr);
                }
            }

            int row0 = wm*16 + qrow;
            float rs0 = 1.f / (Ssum[row0    ] + Ssum[64 + row0    ]);
            float rs1 = 1.f / (Ssum[row0 + 8] + Ssum[64 + row0 + 8]);
            #pragma unroll
            for (int nt = 0; nt < 2; ++nt) {
                int col = h*HD + wn*16 + nt*8 + 2*qcol;
                *(float2*)&As[(row0    )*196 + col] =
                    make_float2(tf32f(o[nt][0]*rs0), tf32f(o[nt][1]*rs0));
                *(float2*)&As[(row0 + 8)*196 + col] =
                    make_float2(tf32f(o[nt][2]*rs1), tf32f(o[nt][3]*rs1));
            }
            __syncthreads();
        }
    }

    // ---------- proj GEMM: C[64x192] = Os(As) @ proj_w^T ----------
    {
        const int wm = warp & 1;
        const int wn = warp >> 1;
        float* Os = As;

        float acc[2][6][4];
        #pragma unroll
        for (int i = 0; i < 2; ++i)
            #pragma unroll
            for (int j = 0; j < 6; ++j)
                #pragma unroll
                for (int r = 0; r < 4; ++r) acc[i][j][r] = 0.f;

        float4 wreg[3];
        #pragma unroll
        for (int i = 0; i < 3; ++i) {
            int idx = i*256 + tid;
            int r2 = idx >> 2, q2 = (idx & 3) << 2;
            wreg[i] = *(const float4*)(proj_w + (size_t)r2 * CC + q2);
        }
        #pragma unroll
        for (int i = 0; i < 3; ++i) {
            int idx = i*256 + tid;
            int r2 = idx >> 2, q2 = (idx & 3) << 2;
            float* d = Bs + 0*192*20 + r2*20 + q2;
            d[0] = tf32f(wreg[i].x); d[1] = tf32f(wreg[i].y);
            d[2] = tf32f(wreg[i].z); d[3] = tf32f(wreg[i].w);
        }
        __syncthreads();

        int buf = 0;
        for (int k0 = 0; ; k0 += 16) {
            const bool more = (k0 + 16) < CC;
            if (more) {
                #pragma unroll
                for (int i = 0; i < 3; ++i) {
                    int idx = i*256 + tid;
                    int r2 = idx >> 2, q2 = (idx & 3) << 2;
                    wreg[i] = *(const float4*)(proj_w + (size_t)r2 * CC + k0 + 16 + q2);
                }
            }
            #pragma unroll
            for (int ks = 0; ks < 16; ks += 8) {
                uint32_t afr[2][4];
                #pragma unroll
                for (int mt = 0; mt < 2; ++mt) {
                    int r = wm*32 + mt*16 + qrow;
                    int k = k0 + ks + qcol;
                    afr[mt][0] = __float_as_uint(Os[r*196     + k]);
                    afr[mt][1] = __float_as_uint(Os[(r+8)*196 + k]);
                    afr[mt][2] = __float_as_uint(Os[r*196     + k + 4]);
                    afr[mt][3] = __float_as_uint(Os[(r+8)*196 + k + 4]);
                }
                uint32_t bfr[6][2];
                #pragma unroll
                for (int nt = 0; nt < 6; ++nt) {
                    int n = wn*48 + nt*8 + qrow;
                    bfr[nt][0] = __float_as_uint(Bs[buf*192*20 + n*20 + ks + qcol]);
                    bfr[nt][1] = __float_as_uint(Bs[buf*192*20 + n*20 + ks + qcol + 4]);
                }
                #pragma unroll
                for (int mt = 0; mt < 2; ++mt)
                    #pragma unroll
                    for (int nt = 0; nt < 6; ++nt)
                        mma_tf32(acc[mt][nt], afr[mt], bfr[nt]);
            }
            if (!more) break;
            const int ob = buf ^ 1;
            #pragma unroll
            for (int i = 0; i < 3; ++i) {
                int idx = i*256 + tid;
                int r2 = idx >> 2, q2 = (idx & 3) << 2;
                float* d = Bs + ob*192*20 + r2*20 + q2;
                d[0] = tf32f(wreg[i].x); d[1] = tf32f(wreg[i].y);
                d[2] = tf32f(wreg[i].z); d[3] = tf32f(wreg[i].w);
            }
            __syncthreads();
            buf = ob;
        }

        // epilogue: +bias, +x residual, window-reverse to token order
        #pragma unroll
        for (int mt = 0; mt < 2; ++mt) {
            #pragma unroll
            for (int half = 0; half < 2; ++half) {
                int lrow = wm*32 + mt*16 + qrow + half*8;
                size_t orow = win_to_tok(tok0 + lrow);
                #pragma unroll
                for (int nt = 0; nt < 6; ++nt) {
                    #pragma unroll
                    for (int e = 0; e < 2; ++e) {
                        int col = wn*48 + nt*8 + qcol*2 + e;
                        float v = acc[mt][nt][half*2 + e] + proj_b[col]
                                + x[orow * CC + col];
                        x1[orow * CC + col] = v;
                    }
                }
            }
        }
    }
}

// ---------------- fused LN2 + MLP1 + GELU + MLP2 + residual (unchanged) ----------------
__global__ __launch_bounds__(256, 2) void fused_mlp_k(
    const float* __restrict__ x1, const float* __restrict__ n2g,
    const float* __restrict__ n2b, const float* __restrict__ w1,
    const float* __restrict__ b1, const float* __restrict__ w2,
    const float* __restrict__ b2, float* __restrict__ out)
{
    extern __shared__ float smem[];
    float* As = smem;                 // [64][196]
    float* Hs = As + 64*196;          // [64][68]
    float* Ws = Hs + 64*68;           // [2][192][20]

    const int row0 = blockIdx.x * 64;
    const int tid  = threadIdx.x;
    const int lane = tid & 31;
    const int warp = tid >> 5;
    const int qrow = lane >> 2;
    const int qcol = lane & 3;
    const int wm = warp & 1;
    const int wn = warp >> 1;

    #pragma unroll
    for (int rr = 0; rr < 8; ++rr) {
        int row = warp*8 + rr;
        const float* src = x1 + (size_t)(row0 + row) * CC;
        float v[6];
        float s = 0.f;
        #pragma unroll
        for (int u = 0; u < 6; ++u) { v[u] = src[lane + u*32]; s += v[u]; }
        #pragma unroll
        for (int o = 16; o; o >>= 1) s += __shfl_xor_sync(0xffffffffu, s, o);
        float mean = s * (1.f/192.f);
        float var = 0.f;
        #pragma unroll
        for (int u = 0; u < 6; ++u) { float d = v[u]-mean; var += d*d; }
        #pragma unroll
        for (int o = 16; o; o >>= 1) var += __shfl_xor_sync(0xffffffffu, var, o);
        var *= (1.f/192.f);
        float rstd = rsqrtf(var + 1e-5f);
        #pragma unroll
        for (int u = 0; u < 6; ++u) {
            int ch = lane + u*32;
            As[row*196 + ch] = tf32f((v[u]-mean)*rstd*n2g[ch] + n2b[ch]);
        }
    }
    __syncthreads();

    float accC[2][6][4];
    #pragma unroll
    for (int i = 0; i < 2; ++i)
        #pragma unroll
        for (int j = 0; j < 6; ++j)
            #pragma unroll
            for (int r = 0; r < 4; ++r) accC[i][j][r] = 0.f;

    const int r1 = tid >> 2;
    const int q1 = (tid & 3) << 2;

    for (int hc = 0; hc < 12; ++hc) {
        float accH[2][2][4];
        #pragma unroll
        for (int i = 0; i < 2; ++i)
            #pragma unroll
            for (int j = 0; j < 2; ++j)
                #pragma unroll
                for (int r = 0; r < 4; ++r) accH[i][j][r] = 0.f;

        const float* W1p = w1 + (size_t)(hc*64 + r1) * CC + q1;
        float4 wreg = *(const float4*)(W1p);
        {
            float* d = Ws + 0*192*20 + r1*20 + q1;
            d[0] = tf32f(wreg.x); d[1] = tf32f(wreg.y);
            d[2] = tf32f(wreg.z); d[3] = tf32f(wreg.w);
        }
        __syncthreads();
        int buf = 0;
        for (int k0 = 0; ; k0 += 16) {
            const bool more = (k0 + 16) < CC;
            if (more) wreg = *(const float4*)(W1p + k0 + 16);
            #pragma unroll
            for (int ks = 0; ks < 16; ks += 8) {
                uint32_t afr[2][4];
                #pragma unroll
                for (int mt = 0; mt < 2; ++mt) {
                    int r = wm*32 + mt*16 + qrow;
                    int k = k0 + ks + qcol;
                    afr[mt][0] = __float_as_uint(As[r*196     + k]);
                    afr[mt][1] = __float_as_uint(As[(r+8)*196 + k]);
                    afr[mt][2] = __float_as_uint(As[r*196     + k + 4]);
                    afr[mt][3] = __float_as_uint(As[(r+8)*196 + k + 4]);
                }
                uint32_t bfr[2][2];
                #pragma unroll
                for (int nt = 0; nt < 2; ++nt) {
                    int n = wn*16 + nt*8 + qrow;
                    bfr[nt][0] = __float_as_uint(Ws[buf*192*20 + n*20 + ks + qcol]);
                    bfr[nt][1] = __float_as_uint(Ws[buf*192*20 + n*20 + ks + qcol + 4]);
                }
                #pragma unroll
                for (int mt = 0; mt < 2; ++mt)
                    #pragma unroll
                    for (int nt = 0; nt < 2; ++nt)
                        mma_tf32(accH[mt][nt], afr[mt], bfr[nt]);
            }
            if (!more) break;
            const int ob = buf ^ 1;
            float* d = Ws + ob*192*20 + r1*20 + q1;
            d[0] = tf32f(wreg.x); d[1] = tf32f(wreg.y);
            d[2] = tf32f(wreg.z); d[3] = tf32f(wreg.w);
            __syncthreads();
            buf = ob;
        }
        __syncthreads();

        #pragma unroll
        for (int mt = 0; mt < 2; ++mt) {
            #pragma unroll
            for (int nt = 0; nt < 2; ++nt) {
                #pragma unroll
                for (int half = 0; half < 2; ++half) {
                    int row = wm*32 + mt*16 + qrow + half*8;
                    #pragma unroll
                    for (int e = 0; e < 2; ++e) {
                        int col = wn*16 + nt*8 + qcol*2 + e;
                        float v = accH[mt][nt][half*2 + e] + b1[hc*64 + col];
                        v = 0.5f * v * (1.0f + erff(v * 0.70710678118654752f));
                        Hs[row*68 + col] = tf32f(v);
                    }
                }
            }
        }
        __syncthreads();

        float4 w2reg[3];
        #pragma unroll
        for (int i = 0; i < 3; ++i) {
            int idx = i*256 + tid;
            int r2 = idx >> 2, q2 = (idx & 3) << 2;
            w2reg[i] = *(const float4*)(w2 + (size_t)r2 * (4*CC) + hc*64 + q2);
        }
        #pragma unroll
        for (int i = 0; i < 3; ++i) {
            int idx = i*256 + tid;
            int r2 = idx >> 2, q2 = (idx & 3) << 2;
            float* d = Ws + 0*192*20 + r2*20 + q2;
            d[0] = tf32f(w2reg[i].x); d[1] = tf32f(w2reg[i].y);
            d[2] = tf32f(w2reg[i].z); d[3] = tf32f(w2reg[i].w);
        }
        __syncthreads();
        buf = 0;
        for (int k2 = 0; ; k2 += 16) {
            const bool more = (k2 + 16) < 64;
            if (more) {
                #pragma unroll
                for (int i = 0; i < 3; ++i) {
                    int idx = i*256 + tid;
                    int r2 = idx >> 2, q2 = (idx & 3) << 2;
                    w2reg[i] = *(const float4*)(w2 + (size_t)r2 * (4*CC) + hc*64 + k2 + 16 + q2);
                }
            }
            #pragma unroll
            for (int ks = 0; ks < 16; ks += 8) {
                uint32_t afr[2][4];
                #pragma unroll
                for (int mt = 0; mt < 2; ++mt) {
                    int r = wm*32 + mt*16 + qrow;
                    int k = k2 + ks + qcol;
                    afr[mt][0] = __float_as_uint(Hs[r*68     + k]);
                    afr[mt][1] = __float_as_uint(Hs[(r+8)*68 + k]);
                    afr[mt][2] = __float_as_uint(Hs[r*68     + k + 4]);
                    afr[mt][3] = __float_as_uint(Hs[(r+8)*68 + k + 4]);
                }
                uint32_t bfr[6][2];
                #pragma unroll
                for (int nt = 0; nt < 6; ++nt) {
                    int n = wn*48 + nt*8 + qrow;
                    bfr[nt][0] = __float_as_uint(Ws[buf*192*20 + n*20 + ks + qcol]);
                    bfr[nt][1] = __float_as_uint(Ws[buf*192*20 + n*20 + ks + qcol + 4]);
                }
                #pragma unroll
                for (int mt = 0; mt < 2; ++mt)
                    #pragma unroll
                    for (int nt = 0; nt < 6; ++nt)
                        mma_tf32(accC[mt][nt], afr[mt], bfr[nt]);
            }
            if (!more) break;
            const int ob = buf ^ 1;
            #pragma unroll
            for (int i = 0; i < 3; ++i) {
                int idx = i*256 + tid;
                int r2 = idx >> 2, q2 = (idx & 3) << 2;
                float* d = Ws + ob*192*20 + r2*20 + q2;
                d[0] = tf32f(w2reg[i].x); d[1] = tf32f(w2reg[i].y);
                d[2] = tf32f(w2reg[i].z); d[3] = tf32f(w2reg[i].w);
            }
            __syncthreads();
            buf = ob;
        }
        __syncthreads();
    }

    #pragma unroll
    for (int mt = 0; mt < 2; ++mt) {
        #pragma unroll
        for (int half = 0; half < 2; ++half) {
            int row = row0 + wm*32 + mt*16 + qrow + half*8;
            #pragma unroll
            for (int nt = 0; nt < 6; ++nt) {
                #pragma unroll
                for (int e = 0; e < 2; ++e) {
                    int col = wn*48 + nt*8 + qcol*2 + e;
                    float v = accC[mt][nt][half*2 + e] + b2[col]
                            + x1[(size_t)row * CC + col];
                    out[(size_t)row * CC + col] = v;
                }
            }
        }
    }
}

// ---------------- host launcher ----------------
extern "C" void kernel_launch(void* const* d_in, const int* in_sizes, int n_in,
                              void* d_out, int out_size)
{
    const float* x      = (const float*)d_in[0];
    const float* qkv_w  = (const float*)d_in[1];
    const float* qkv_b  = (const float*)d_in[2];
    const float* proj_w = (const float*)d_in[3];
    const float* proj_b = (const float*)d_in[4];
    const float* n1_g   = (const float*)d_in[5];
    const float* n1_b   = (const float*)d_in[6];
    const float* n2_g   = (const float*)d_in[7];
    const float* n2_b   = (const float*)d_in[8];
    const float* w1     = (const float*)d_in[9];
    const float* b1     = (const float*)d_in[10];
    const float* w2     = (const float*)d_in[11];
    const float* b2     = (const float*)d_in[12];
    float* out = (float*)d_out;

    float* x1;
    cudaGetSymbolAddress((void**)&x1, g_x1);

    const int P1_SMEM  = (4*R196 + 2*192*20) * 4;             // 231424 B
    const int MLP_SMEM = (64*196 + 64*68 + 2*192*20) * 4;     // 98304 B
    cudaFuncSetAttribute(swin_part1_k, cudaFuncAttributeMaxDynamicSharedMemorySize, P1_SMEM);
    cudaFuncSetAttribute(fused_mlp_k,  cudaFuncAttributeMaxDynamicSharedMemorySize, MLP_SMEM);

    // 1) megakernel: LN1 + QKV + attention + proj + window-reverse + residual -> x1
    swin_part1_k<<<NWIN, 256, P1_SMEM>>>(x, n1_g, n1_b, qkv_w, qkv_b,
                                         proj_w, proj_b, x1);

    // 2) fused LN2 + MLP1 + GELU + MLP2 + residual -> out
    fused_mlp_k<<<NTOK/64, 256, MLP_SMEM>>>(x1, n2_g, n2_b, w1, b1, w2, b2, out);
}

// round 12
// speedup vs baseline: 1.0942x; 1.0942x over previous
#include <cuda_runtime.h>
#include <cuda_bf16.h>
#include <cstdint>
#include <cstdio>

// ---------------- problem constants ----------------
#define BIMG   16
#define HH     128
#define WW_    128
#define CC     192
#define HEADS  6
#define HD     32
#define WIN    8
#define SHIFT  4
#define NTOK   (BIMG * HH * WW_)              // 262144 tokens
#define NWIN   (BIMG * (HH/WIN) * (WW_/WIN))  // 4096 windows
#define NN     (WIN * WIN)                    // 64 tokens per window

// ---------------- scratch ----------------
__device__ float g_qkv [ (size_t)NTOK * 3 * CC ];   // window-order qkv
__device__ float g_x1  [ (size_t)NTOK * CC ];       // residual-1 (token order)

// ---------------- helpers ----------------
__device__ __forceinline__ float tf32f(float x) {
    uint32_t u;
    asm("cvt.rna.tf32.f32 %0, %1;" : "=r"(u) : "f"(x));
    return __uint_as_float(u);
}

__device__ __forceinline__ void mma_tf32(float c[4], const uint32_t a[4], const uint32_t b[2]) {
    asm volatile(
        "mma.sync.aligned.m16n8k8.row.col.f32.tf32.tf32.f32 "
        "{%0,%1,%2,%3}, {%4,%5,%6,%7}, {%8,%9}, {%0,%1,%2,%3};"
        : "+f"(c[0]), "+f"(c[1]), "+f"(c[2]), "+f"(c[3])
        : "r"(a[0]), "r"(a[1]), "r"(a[2]), "r"(a[3]), "r"(b[0]), "r"(b[1]));
}

// exp(x) for |x| <= 0.1768: degree-5 Taylor, rel err < 5e-9
__device__ __forceinline__ float exp_small(float x) {
    float e = 8.3333333e-3f;
    e = e * x + 4.1666667e-2f;
    e = e * x + 1.6666667e-1f;
    e = e * x + 0.5f;
    e = e * x + 1.0f;
    e = e * x + 1.0f;
    return e;
}

// window-order token -> original token row (shift + window reverse)
__device__ __forceinline__ size_t win_to_tok(int tok) {
    int win = tok >> 6, n = tok & 63;
    int b   = win >> 8;
    int wh  = (win >> 4) & 15;
    int ww  = win & 15;
    int r   = n >> 3, c = n & 7;
    int i = (wh*WIN + r + SHIFT) & 127;
    int j = (ww*WIN + c + SHIFT) & 127;
    return (size_t)b * (HH*WW_) + (size_t)i * WW_ + j;
}

// ---------------- fused LN1(+shift gather) + QKV GEMM (R10-proven) ----------------
__global__ __launch_bounds__(256) void ln1_qkv_k(
    const float* __restrict__ x, const float* __restrict__ n1g,
    const float* __restrict__ n1b, const float* __restrict__ qkv_w,
    const float* __restrict__ qkv_b, float* __restrict__ qkv)
{
    __shared__ float As[64*196];
    __shared__ float Bs[2*192*20];

    const int tok0 = blockIdx.x * 64;
    const int tid  = threadIdx.x;
    const int lane = tid & 31;
    const int warp = tid >> 5;
    const int qrow = lane >> 2;
    const int qcol = lane & 3;
    const int wm = warp & 1;
    const int wn = warp >> 1;

    #pragma unroll
    for (int rr = 0; rr < 8; ++rr) {
        int row = warp*8 + rr;
        const float* src = x + win_to_tok(tok0 + row) * CC;
        float v[6];
        float s = 0.f;
        #pragma unroll
        for (int u = 0; u < 6; ++u) { v[u] = src[lane + u*32]; s += v[u]; }
        #pragma unroll
        for (int o = 16; o; o >>= 1) s += __shfl_xor_sync(0xffffffffu, s, o);
        float mean = s * (1.f/192.f);
        float var = 0.f;
        #pragma unroll
        for (int u = 0; u < 6; ++u) { float d = v[u]-mean; var += d*d; }
        #pragma unroll
        for (int o = 16; o; o >>= 1) var += __shfl_xor_sync(0xffffffffu, var, o);
        var *= (1.f/192.f);
        float rstd = rsqrtf(var + 1e-5f);
        #pragma unroll
        for (int u = 0; u < 6; ++u) {
            int ch = lane + u*32;
            As[row*196 + ch] = tf32f((v[u]-mean)*rstd*n1g[ch] + n1b[ch]);
        }
    }
    __syncthreads();

    for (int nc = 0; nc < 3; ++nc) {
        float acc[2][6][4];
        #pragma unroll
        for (int i = 0; i < 2; ++i)
            #pragma unroll
            for (int j = 0; j < 6; ++j)
                #pragma unroll
                for (int r = 0; r < 4; ++r) acc[i][j][r] = 0.f;

        float4 wreg[3];
        #pragma unroll
        for (int i = 0; i < 3; ++i) {
            int idx = i*256 + tid;
            int r2 = idx >> 2, q2 = (idx & 3) << 2;
            wreg[i] = *(const float4*)(qkv_w + (size_t)(nc*192 + r2) * CC + q2);
        }
        #pragma unroll
        for (int i = 0; i < 3; ++i) {
            int idx = i*256 + tid;
            int r2 = idx >> 2, q2 = (idx & 3) << 2;
            float* d = Bs + 0*192*20 + r2*20 + q2;
            d[0] = tf32f(wreg[i].x); d[1] = tf32f(wreg[i].y);
            d[2] = tf32f(wreg[i].z); d[3] = tf32f(wreg[i].w);
        }
        __syncthreads();

        int buf = 0;
        for (int k0 = 0; ; k0 += 16) {
            const bool more = (k0 + 16) < CC;
            if (more) {
                #pragma unroll
                for (int i = 0; i < 3; ++i) {
                    int idx = i*256 + tid;
                    int r2 = idx >> 2, q2 = (idx & 3) << 2;
                    wreg[i] = *(const float4*)(qkv_w + (size_t)(nc*192 + r2) * CC + k0 + 16 + q2);
                }
            }
            #pragma unroll
            for (int ks = 0; ks < 16; ks += 8) {
                uint32_t afr[2][4];
                #pragma unroll
                for (int mt = 0; mt < 2; ++mt) {
                    int r = wm*32 + mt*16 + qrow;
                    int k = k0 + ks + qcol;
                    afr[mt][0] = __float_as_uint(As[r*196     + k]);
                    afr[mt][1] = __float_as_uint(As[(r+8)*196 + k]);
                    afr[mt][2] = __float_as_uint(As[r*196     + k + 4]);
                    afr[mt][3] = __float_as_uint(As[(r+8)*196 + k + 4]);
                }
                uint32_t bfr[6][2];
                #pragma unroll
                for (int nt = 0; nt < 6; ++nt) {
                    int n = wn*48 + nt*8 + qrow;
                    bfr[nt][0] = __float_as_uint(Bs[buf*192*20 + n*20 + ks + qcol]);
                    bfr[nt][1] = __float_as_uint(Bs[buf*192*20 + n*20 + ks + qcol + 4]);
                }
                #pragma unroll
                for (int mt = 0; mt < 2; ++mt)
                    #pragma unroll
                    for (int nt = 0; nt < 6; ++nt)
                        mma_tf32(acc[mt][nt], afr[mt], bfr[nt]);
            }
            if (!more) break;
            const int ob = buf ^ 1;
            #pragma unroll
            for (int i = 0; i < 3; ++i) {
                int idx = i*256 + tid;
                int r2 = idx >> 2, q2 = (idx & 3) << 2;
                float* d = Bs + ob*192*20 + r2*20 + q2;
                d[0] = tf32f(wreg[i].x); d[1] = tf32f(wreg[i].y);
                d[2] = tf32f(wreg[i].z); d[3] = tf32f(wreg[i].w);
            }
            __syncthreads();
            buf = ob;
        }
        __syncthreads();

        #pragma unroll
        for (int mt = 0; mt < 2; ++mt) {
            #pragma unroll
            for (int half = 0; half < 2; ++half) {
                int row = tok0 + wm*32 + mt*16 + qrow + half*8;
                #pragma unroll
                for (int nt = 0; nt < 6; ++nt) {
                    int col = nc*192 + wn*48 + nt*8 + qcol*2;
                    float2 v = make_float2(
                        acc[mt][nt][half*2 + 0] + qkv_b[col],
                        acc[mt][nt][half*2 + 1] + qkv_b[col + 1]);
                    *(float2*)&qkv[(size_t)row * (3*CC) + col] = v;
                }
            }
        }
    }
}

// ---------------- fused attention + proj + window-reverse + residual (R10-proven) ----------------
__global__ __launch_bounds__(256) void attn_proj_k(
    const float* __restrict__ qkv, const float* __restrict__ proj_w,
    const float* __restrict__ proj_b, const float* __restrict__ x,
    float* __restrict__ x1)
{
    extern __shared__ float sm[];
    float* Qs   = sm;                  // [64][36]
    float* Ks   = Qs + 64*36;          // [64][36]
    float* Vs   = Ks + 64*36;          // [32][68]
    float* Ps   = Vs + 32*68;          // [64][68]
    float* Ssum = Ps + 64*68;          // [2][64]
    float* Os   = sm + 11264;          // [64][196]
    float* Wb   = sm;                  // [2][192][20] overlay

    const int win  = blockIdx.x;
    const int tid  = threadIdx.x;
    const int lane = tid & 31;
    const int warp = tid >> 5;
    const int qrow = lane >> 2;
    const int qcol = lane & 3;
    const int wm   = warp >> 1;
    const int wn   = warp & 1;
    const int sr   = tid >> 2;
    const int sq   = tid & 3;

    const float scale = 0.17677669529663687f;

    for (int h = 0; h < HEADS; ++h) {
        {
            const float* rowp = qkv + (size_t)(win*NN + sr)*(3*CC) + h*HD + sq*8;
            float4 qa = *(const float4*)(rowp);
            float4 qb = *(const float4*)(rowp + 4);
            float ss = qa.x*qa.x + qa.y*qa.y + qa.z*qa.z + qa.w*qa.w
                     + qb.x*qb.x + qb.y*qb.y + qb.z*qb.z + qb.w*qb.w;
            ss += __shfl_xor_sync(0xffffffffu, ss, 1);
            ss += __shfl_xor_sync(0xffffffffu, ss, 2);
            float invq = scale / fmaxf(sqrtf(ss), 1e-12f);
            Qs[sr*36 + sq*8+0] = tf32f(qa.x*invq); Qs[sr*36 + sq*8+1] = tf32f(qa.y*invq);
            Qs[sr*36 + sq*8+2] = tf32f(qa.z*invq); Qs[sr*36 + sq*8+3] = tf32f(qa.w*invq);
            Qs[sr*36 + sq*8+4] = tf32f(qb.x*invq); Qs[sr*36 + sq*8+5] = tf32f(qb.y*invq);
            Qs[sr*36 + sq*8+6] = tf32f(qb.z*invq); Qs[sr*36 + sq*8+7] = tf32f(qb.w*invq);

            float4 ka = *(const float4*)(rowp + CC);
            float4 kb = *(const float4*)(rowp + CC + 4);
            float sk = ka.x*ka.x + ka.y*ka.y + ka.z*ka.z + ka.w*ka.w
                     + kb.x*kb.x + kb.y*kb.y + kb.z*kb.z + kb.w*kb.w;
            sk += __shfl_xor_sync(0xffffffffu, sk, 1);
            sk += __shfl_xor_sync(0xffffffffu, sk, 2);
            float invk = 1.f / fmaxf(sqrtf(sk), 1e-12f);
            Ks[sr*36 + sq*8+0] = tf32f(ka.x*invk); Ks[sr*36 + sq*8+1] = tf32f(ka.y*invk);
            Ks[sr*36 + sq*8+2] = tf32f(ka.z*invk); Ks[sr*36 + sq*8+3] = tf32f(ka.w*invk);
            Ks[sr*36 + sq*8+4] = tf32f(kb.x*invk); Ks[sr*36 + sq*8+5] = tf32f(kb.y*invk);
            Ks[sr*36 + sq*8+6] = tf32f(kb.z*invk); Ks[sr*36 + sq*8+7] = tf32f(kb.w*invk);

            float4 va = *(const float4*)(rowp + 2*CC);
            float4 vb = *(const float4*)(rowp + 2*CC + 4);
            Vs[(sq*8+0)*68 + sr] = tf32f(va.x); Vs[(sq*8+1)*68 + sr] = tf32f(va.y);
            Vs[(sq*8+2)*68 + sr] = tf32f(va.z); Vs[(sq*8+3)*68 + sr] = tf32f(va.w);
            Vs[(sq*8+4)*68 + sr] = tf32f(vb.x); Vs[(sq*8+5)*68 + sr] = tf32f(vb.y);
            Vs[(sq*8+6)*68 + sr] = tf32f(vb.z); Vs[(sq*8+7)*68 + sr] = tf32f(vb.w);
        }
        __syncthreads();

        float c[4][4];
        #pragma unroll
        for (int nt = 0; nt < 4; ++nt)
            #pragma unroll
            for (int i = 0; i < 4; ++i) c[nt][i] = 0.f;
        #pragma unroll
        for (int ks = 0; ks < 32; ks += 8) {
            uint32_t afr[4];
            int r = wm*16 + qrow;
            afr[0] = __float_as_uint(Qs[r*36     + ks + qcol    ]);
            afr[1] = __float_as_uint(Qs[(r+8)*36 + ks + qcol    ]);
            afr[2] = __float_as_uint(Qs[r*36     + ks + qcol + 4]);
            afr[3] = __float_as_uint(Qs[(r+8)*36 + ks + qcol + 4]);
            #pragma unroll
            for (int nt = 0; nt < 4; ++nt) {
                uint32_t bfr[2];
                int n = wn*32 + nt*8 + qrow;
                bfr[0] = __float_as_uint(Ks[n*36 + ks + qcol    ]);
                bfr[1] = __float_as_uint(Ks[n*36 + ks + qcol + 4]);
                mma_tf32(c[nt], afr, bfr);
            }
        }

        float s0 = 0.f, s1 = 0.f;
        #pragma unroll
        for (int nt = 0; nt < 4; ++nt) {
            c[nt][0] = exp_small(c[nt][0]);
            c[nt][1] = exp_small(c[nt][1]);
            c[nt][2] = exp_small(c[nt][2]);
            c[nt][3] = exp_small(c[nt][3]);
            s0 += c[nt][0] + c[nt][1];
            s1 += c[nt][2] + c[nt][3];
        }
        s0 += __shfl_xor_sync(0xffffffffu, s0, 1);
        s0 += __shfl_xor_sync(0xffffffffu, s0, 2);
        s1 += __shfl_xor_sync(0xffffffffu, s1, 1);
        s1 += __shfl_xor_sync(0xffffffffu, s1, 2);
        if (qcol == 0) {
            Ssum[wn*64 + wm*16 + qrow    ] = s0;
            Ssum[wn*64 + wm*16 + qrow + 8] = s1;
        }
        #pragma unroll
        for (int nt = 0; nt < 4; ++nt) {
            int col = wn*32 + nt*8 + 2*qcol;
            *(float2*)&Ps[(wm*16 + qrow    )*68 + col] =
                make_float2(tf32f(c[nt][0]), tf32f(c[nt][1]));
            *(float2*)&Ps[(wm*16 + qrow + 8)*68 + col] =
                make_float2(tf32f(c[nt][2]), tf32f(c[nt][3]));
        }
        __syncthreads();

        float o[2][4];
        #pragma unroll
        for (int nt = 0; nt < 2; ++nt)
            #pragma unroll
            for (int i = 0; i < 4; ++i) o[nt][i] = 0.f;
        #pragma unroll
        for (int ks = 0; ks < 64; ks += 8) {
            uint32_t afr[4];
            int r = wm*16 + qrow;
            afr[0] = __float_as_uint(Ps[r*68     + ks + qcol    ]);
            afr[1] = __float_as_uint(Ps[(r+8)*68 + ks + qcol    ]);
            afr[2] = __float_as_uint(Ps[r*68     + ks + qcol + 4]);
            afr[3] = __float_as_uint(Ps[(r+8)*68 + ks + qcol + 4]);
            #pragma unroll
            for (int nt = 0; nt < 2; ++nt) {
                uint32_t bfr[2];
                int n = wn*16 + nt*8 + qrow;
                bfr[0] = __float_as_uint(Vs[n*68 + ks + qcol    ]);
                bfr[1] = __float_as_uint(Vs[n*68 + ks + qcol + 4]);
                mma_tf32(o[nt], afr, bfr);
            }
        }

        int row0 = wm*16 + qrow;
        float rs0 = 1.f / (Ssum[row0    ] + Ssum[64 + row0    ]);
        float rs1 = 1.f / (Ssum[row0 + 8] + Ssum[64 + row0 + 8]);
        #pragma unroll
        for (int nt = 0; nt < 2; ++nt) {
            int col = h*HD + wn*16 + nt*8 + 2*qcol;
            *(float2*)&Os[(row0    )*196 + col] =
                make_float2(tf32f(o[nt][0]*rs0), tf32f(o[nt][1]*rs0));
            *(float2*)&Os[(row0 + 8)*196 + col] =
                make_float2(tf32f(o[nt][2]*rs1), tf32f(o[nt][3]*rs1));
        }
        __syncthreads();
    }

    const int wm2 = warp & 1;
    const int wn2 = warp >> 1;

    float acc[2][6][4];
    #pragma unroll
    for (int i = 0; i < 2; ++i)
        #pragma unroll
        for (int j = 0; j < 6; ++j)
            #pragma unroll
            for (int r = 0; r < 4; ++r) acc[i][j][r] = 0.f;

    float4 wreg[3];
    #pragma unroll
    for (int i = 0; i < 3; ++i) {
        int idx = i*256 + tid;
        int r2 = idx >> 2, q2 = (idx & 3) << 2;
        wreg[i] = *(const float4*)(proj_w + (size_t)r2 * CC + q2);
    }
    #pragma unroll
    for (int i = 0; i < 3; ++i) {
        int idx = i*256 + tid;
        int r2 = idx >> 2, q2 = (idx & 3) << 2;
        float* d = Wb + 0*192*20 + r2*20 + q2;
        d[0] = tf32f(wreg[i].x); d[1] = tf32f(wreg[i].y);
        d[2] = tf32f(wreg[i].z); d[3] = tf32f(wreg[i].w);
    }
    __syncthreads();

    int buf = 0;
    for (int k0 = 0; ; k0 += 16) {
        const bool more = (k0 + 16) < CC;
        if (more) {
            #pragma unroll
            for (int i = 0; i < 3; ++i) {
                int idx = i*256 + tid;
                int r2 = idx >> 2, q2 = (idx & 3) << 2;
                wreg[i] = *(const float4*)(proj_w + (size_t)r2 * CC + k0 + 16 + q2);
            }
        }
        #pragma unroll
        for (int ks = 0; ks < 16; ks += 8) {
            uint32_t afr[2][4];
            #pragma unroll
            for (int mt = 0; mt < 2; ++mt) {
                int r = wm2*32 + mt*16 + qrow;
                int k = k0 + ks + qcol;
                afr[mt][0] = __float_as_uint(Os[r*196     + k]);
                afr[mt][1] = __float_as_uint(Os[(r+8)*196 + k]);
                afr[mt][2] = __float_as_uint(Os[r*196     + k + 4]);
                afr[mt][3] = __float_as_uint(Os[(r+8)*196 + k + 4]);
            }
            uint32_t bfr[6][2];
            #pragma unroll
            for (int nt = 0; nt < 6; ++nt) {
                int n = wn2*48 + nt*8 + qrow;
                bfr[nt][0] = __float_as_uint(Wb[buf*192*20 + n*20 + ks + qcol]);
                bfr[nt][1] = __float_as_uint(Wb[buf*192*20 + n*20 + ks + qcol + 4]);
            }
            #pragma unroll
            for (int mt = 0; mt < 2; ++mt)
                #pragma unroll
                for (int nt = 0; nt < 6; ++nt)
                    mma_tf32(acc[mt][nt], afr[mt], bfr[nt]);
        }
        if (!more) break;
        const int ob = buf ^ 1;
        #pragma unroll
        for (int i = 0; i < 3; ++i) {
            int idx = i*256 + tid;
            int r2 = idx >> 2, q2 = (idx & 3) << 2;
            float* d = Wb + ob*192*20 + r2*20 + q2;
            d[0] = tf32f(wreg[i].x); d[1] = tf32f(wreg[i].y);
            d[2] = tf32f(wreg[i].z); d[3] = tf32f(wreg[i].w);
        }
        __syncthreads();
        buf = ob;
    }

    #pragma unroll
    for (int mt = 0; mt < 2; ++mt) {
        #pragma unroll
        for (int half = 0; half < 2; ++half) {
            int lrow = wm2*32 + mt*16 + qrow + half*8;
            size_t orow = win_to_tok(win*NN + lrow);
            #pragma unroll
            for (int nt = 0; nt < 6; ++nt) {
                #pragma unroll
                for (int e = 0; e < 2; ++e) {
                    int col = wn2*48 + nt*8 + qcol*2 + e;
                    float v = acc[mt][nt][half*2 + e] + proj_b[col]
                            + x[orow * CC + col];
                    x1[orow * CC + col] = v;
                }
            }
        }
    }
}

// ---------------- fused LN2 + MLP1 + GELU + MLP2 + residual (hidden chunks of 96) ----------------
__global__ __launch_bounds__(256, 2) void fused_mlp_k(
    const float* __restrict__ x1, const float* __restrict__ n2g,
    const float* __restrict__ n2b, const float* __restrict__ w1,
    const float* __restrict__ b1, const float* __restrict__ w2,
    const float* __restrict__ b2, float* __restrict__ out)
{
    extern __shared__ float smem[];
    float* As = smem;                 // [64][196]
    float* Hs = As + 64*196;          // [64][100]
    float* Ws = Hs + 64*100;          // [2][192][20] (GEMM1 uses [2][96][20] prefix)

    const int row0 = blockIdx.x * 64;
    const int tid  = threadIdx.x;
    const int lane = tid & 31;
    const int warp = tid >> 5;
    const int qrow = lane >> 2;
    const int qcol = lane & 3;
    const int wm = warp & 1;          // 2 m-tiles of 32
    const int wn = warp >> 1;         // 4 n-groups

    // ---- LN2 staging ----
    #pragma unroll
    for (int rr = 0; rr < 8; ++rr) {
        int row = warp*8 + rr;
        const float* src = x1 + (size_t)(row0 + row) * CC;
        float v[6];
        float s = 0.f;
        #pragma unroll
        for (int u = 0; u < 6; ++u) { v[u] = src[lane + u*32]; s += v[u]; }
        #pragma unroll
        for (int o = 16; o; o >>= 1) s += __shfl_xor_sync(0xffffffffu, s, o);
        float mean = s * (1.f/192.f);
        float var = 0.f;
        #pragma unroll
        for (int u = 0; u < 6; ++u) { float d = v[u]-mean; var += d*d; }
        #pragma unroll
        for (int o = 16; o; o >>= 1) var += __shfl_xor_sync(0xffffffffu, var, o);
        var *= (1.f/192.f);
        float rstd = rsqrtf(var + 1e-5f);
        #pragma unroll
        for (int u = 0; u < 6; ++u) {
            int ch = lane + u*32;
            As[row*196 + ch] = tf32f((v[u]-mean)*rstd*n2g[ch] + n2b[ch]);
        }
    }
    __syncthreads();

    float accC[2][6][4];
    #pragma unroll
    for (int i = 0; i < 2; ++i)
        #pragma unroll
        for (int j = 0; j < 6; ++j)
            #pragma unroll
            for (int r = 0; r < 4; ++r) accC[i][j][r] = 0.f;

    for (int hc = 0; hc < 8; ++hc) {          // 8 hidden chunks of 96
        // ======== GEMM1: H[64x96] = As @ W1[hc*96.., :]^T ========
        float accH[2][3][4];
        #pragma unroll
        for (int i = 0; i < 2; ++i)
            #pragma unroll
            for (int j = 0; j < 3; ++j)
                #pragma unroll
                for (int r = 0; r < 4; ++r) accH[i][j][r] = 0.f;

        // stage W1 k-slice [0,16): 96 rows x 16 cols = 384 float4 slots
        float4 w1reg[2];
        #pragma unroll
        for (int i = 0; i < 2; ++i) {
            int idx = i*256 + tid;
            if (idx < 384) {
                int r2 = idx >> 2, q2 = (idx & 3) << 2;
                w1reg[i] = *(const float4*)(w1 + (size_t)(hc*96 + r2) * CC + q2);
            }
        }
        #pragma unroll
        for (int i = 0; i < 2; ++i) {
            int idx = i*256 + tid;
            if (idx < 384) {
                int r2 = idx >> 2, q2 = (idx & 3) << 2;
                float* d = Ws + 0*96*20 + r2*20 + q2;
                d[0] = tf32f(w1reg[i].x); d[1] = tf32f(w1reg[i].y);
                d[2] = tf32f(w1reg[i].z); d[3] = tf32f(w1reg[i].w);
            }
        }
        __syncthreads();
        int buf = 0;
        for (int k0 = 0; ; k0 += 16) {
            const bool more = (k0 + 16) < CC;
            if (more) {
                #pragma unroll
                for (int i = 0; i < 2; ++i) {
                    int idx = i*256 + tid;
                    if (idx < 384) {
                        int r2 = idx >> 2, q2 = (idx & 3) << 2;
                        w1reg[i] = *(const float4*)(w1 + (size_t)(hc*96 + r2) * CC + k0 + 16 + q2);
                    }
                }
            }
            #pragma unroll
            for (int ks = 0; ks < 16; ks += 8) {
                uint32_t afr[2][4];
                #pragma unroll
                for (int mt = 0; mt < 2; ++mt) {
                    int r = wm*32 + mt*16 + qrow;
                    int k = k0 + ks + qcol;
                    afr[mt][0] = __float_as_uint(As[r*196     + k]);
                    afr[mt][1] = __float_as_uint(As[(r+8)*196 + k]);
                    afr[mt][2] = __float_as_uint(As[r*196     + k + 4]);
                    afr[mt][3] = __float_as_uint(As[(r+8)*196 + k + 4]);
                }
                uint32_t bfr[3][2];
                #pragma unroll
                for (int nt = 0; nt < 3; ++nt) {
                    int n = wn*24 + nt*8 + qrow;
                    bfr[nt][0] = __float_as_uint(Ws[buf*96*20 + n*20 + ks + qcol]);
                    bfr[nt][1] = __float_as_uint(Ws[buf*96*20 + n*20 + ks + qcol + 4]);
                }
                #pragma unroll
                for (int mt = 0; mt < 2; ++mt)
                    #pragma unroll
                    for (int nt = 0; nt < 3; ++nt)
                        mma_tf32(accH[mt][nt], afr[mt], bfr[nt]);
            }
            if (!more) break;
            const int ob = buf ^ 1;
            #pragma unroll
            for (int i = 0; i < 2; ++i) {
                int idx = i*256 + tid;
                if (idx < 384) {
                    int r2 = idx >> 2, q2 = (idx & 3) << 2;
                    float* d = Ws + ob*96*20 + r2*20 + q2;
                    d[0] = tf32f(w1reg[i].x); d[1] = tf32f(w1reg[i].y);
                    d[2] = tf32f(w1reg[i].z); d[3] = tf32f(w1reg[i].w);
                }
            }
            __syncthreads();
            buf = ob;
        }
        __syncthreads();

        // ---- bias + GELU -> Hs (tf32) ----
        #pragma unroll
        for (int mt = 0; mt < 2; ++mt) {
            #pragma unroll
            for (int nt = 0; nt < 3; ++nt) {
                #pragma unroll
                for (int half = 0; half < 2; ++half) {
                    int row = wm*32 + mt*16 + qrow + half*8;
                    #pragma unroll
                    for (int e = 0; e < 2; ++e) {
                        int col = wn*24 + nt*8 + qcol*2 + e;
                        float v = accH[mt][nt][half*2 + e] + b1[hc*96 + col];
                        v = 0.5f * v * (1.0f + erff(v * 0.70710678118654752f));
                        Hs[row*100 + col] = tf32f(v);
                    }
                }
            }
        }
        __syncthreads();

        // ======== GEMM2: accC += Hs @ W2[:, hc*96..]^T  (K=96) ========
        float4 w2reg[3];
        #pragma unroll
        for (int i = 0; i < 3; ++i) {
            int idx = i*256 + tid;
            int r2 = idx >> 2, q2 = (idx & 3) << 2;
            w2reg[i] = *(const float4*)(w2 + (size_t)r2 * (4*CC) + hc*96 + q2);
        }
        #pragma unroll
        for (int i = 0; i < 3; ++i) {
            int idx = i*256 + tid;
            int r2 = idx >> 2, q2 = (idx & 3) << 2;
            float* d = Ws + 0*192*20 + r2*20 + q2;
            d[0] = tf32f(w2reg[i].x); d[1] = tf32f(w2reg[i].y);
            d[2] = tf32f(w2reg[i].z); d[3] = tf32f(w2reg[i].w);
        }
        __syncthreads();
        buf = 0;
        for (int k2 = 0; ; k2 += 16) {
            const bool more = (k2 + 16) < 96;
            if (more) {
                #pragma unroll
                for (int i = 0; i < 3; ++i) {
                    int idx = i*256 + tid;
                    int r2 = idx >> 2, q2 = (idx & 3) << 2;
                    w2reg[i] = *(const float4*)(w2 + (size_t)r2 * (4*CC) + hc*96 + k2 + 16 + q2);
                }
            }
            #pragma unroll
            for (int ks = 0; ks < 16; ks += 8) {
                uint32_t afr[2][4];
                #pragma unroll
                for (int mt = 0; mt < 2; ++mt) {
                    int r = wm*32 + mt*16 + qrow;
                    int k = k2 + ks + qcol;
                    afr[mt][0] = __float_as_uint(Hs[r*100     + k]);
                    afr[mt][1] = __float_as_uint(Hs[(r+8)*100 + k]);
                    afr[mt][2] = __float_as_uint(Hs[r*100     + k + 4]);
                    afr[mt][3] = __float_as_uint(Hs[(r+8)*100 + k + 4]);
                }
                uint32_t bfr[6][2];
                #pragma unroll
                for (int nt = 0; nt < 6; ++nt) {
                    int n = wn*48 + nt*8 + qrow;
                    bfr[nt][0] = __float_as_uint(Ws[buf*192*20 + n*20 + ks + qcol]);
                    bfr[nt][1] = __float_as_uint(Ws[buf*192*20 + n*20 + ks + qcol + 4]);
                }
                #pragma unroll
                for (int mt = 0; mt < 2; ++mt)
                    #pragma unroll
                    for (int nt = 0; nt < 6; ++nt)
                        mma_tf32(accC[mt][nt], afr[mt], bfr[nt]);
            }
            if (!more) break;
            const int ob = buf ^ 1;
            #pragma unroll
            for (int i = 0; i < 3; ++i) {
                int idx = i*256 + tid;
                int r2 = idx >> 2, q2 = (idx & 3) << 2;
                float* d = Ws + ob*192*20 + r2*20 + q2;
                d[0] = tf32f(w2reg[i].x); d[1] = tf32f(w2reg[i].y);
                d[2] = tf32f(w2reg[i].z); d[3] = tf32f(w2reg[i].w);
            }
            __syncthreads();
            buf = ob;
        }
        __syncthreads();
    }

    // ---- epilogue: +b2 +x1 residual -> out ----
    #pragma unroll
    for (int mt = 0; mt < 2; ++mt) {
        #pragma unroll
        for (int half = 0; half < 2; ++half) {
            int row = row0 + wm*32 + mt*16 + qrow + half*8;
            #pragma unroll
            for (int nt = 0; nt < 6; ++nt) {
                #pragma unroll
                for (int e = 0; e < 2; ++e) {
                    int col = wn*48 + nt*8 + qcol*2 + e;
                    float v = accC[mt][nt][half*2 + e] + b2[col]
                            + x1[(size_t)row * CC + col];
                    out[(size_t)row * CC + col] = v;
                }
            }
        }
    }
}

// ---------------- host launcher ----------------
extern "C" void kernel_launch(void* const* d_in, const int* in_sizes, int n_in,
                              void* d_out, int out_size)
{
    const float* x      = (const float*)d_in[0];
    const float* qkv_w  = (const float*)d_in[1];
    const float* qkv_b  = (const float*)d_in[2];
    const float* proj_w = (const float*)d_in[3];
    const float* proj_b = (const float*)d_in[4];
    const float* n1_g   = (const float*)d_in[5];
    const float* n1_b   = (const float*)d_in[6];
    const float* n2_g   = (const float*)d_in[7];
    const float* n2_b   = (const float*)d_in[8];
    const float* w1     = (const float*)d_in[9];
    const float* b1     = (const float*)d_in[10];
    const float* w2     = (const float*)d_in[11];
    const float* b2     = (const float*)d_in[12];
    float* out = (float*)d_out;

    float *qkv, *x1;
    cudaGetSymbolAddress((void**)&qkv, g_qkv);
    cudaGetSymbolAddress((void**)&x1,  g_x1);

    const int AP_SMEM   = (11264 + 64*196) * 4;               // 95232 B
    const int MLP_SMEM  = (64*196 + 64*100 + 2*192*20) * 4;   // 106496 B
    cudaFuncSetAttribute(attn_proj_k, cudaFuncAttributeMaxDynamicSharedMemorySize, AP_SMEM);
    cudaFuncSetAttribute(fused_mlp_k, cudaFuncAttributeMaxDynamicSharedMemorySize, MLP_SMEM);

    // 1) fused LN1+shift + QKV GEMM -> qkv (window order)
    ln1_qkv_k<<<NTOK/64, 256>>>(x, n1_g, n1_b, qkv_w, qkv_b, qkv);

    // 2) fused attention + proj + window-reverse + residual -> x1 (token order)
    attn_proj_k<<<NWIN, 256, AP_SMEM>>>(qkv, proj_w, proj_b, x, x1);

    // 3) fused LN2 + MLP1 + GELU + MLP2 + residual -> out
    fused_mlp_k<<<NTOK/64, 256, MLP_SMEM>>>(x1, n2_g, n2_b, w1, b1, w2, b2, out);
}